// round 15
// baseline (speedup 1.0000x reference)
#include <cuda_runtime.h>
#include <cuda_fp16.h>
#include <cstdint>

// Shapes (fixed)
constexpr int N_  = 128;
constexpr int L_  = 256;
constexpr int DM  = 256;
constexpr int DP  = 128;

// Device scratch (fp16)
__device__ __half g_A[8192 * 128];   // [(l*32+i)][s]
__device__ __half g_B[8192 * 128];   // [(m*32+j)][s]
__device__ __half g_Wt[DP * 1024];   // [n][ij]

// Dependency flags (reset each launch by reset_kernel)
__device__ int g_flagL[256];         // ln CTA l wrote g_A/g_B rows + its wt slice
__device__ int g_wctr[8];            // # of ln CTAs done in group c (W chunk c ready @32)

// ---------------------------------------------------------------------------
// helpers
// ---------------------------------------------------------------------------
__device__ __forceinline__ uint32_t smem_u32(const void* p) {
    uint32_t a;
    asm("{ .reg .u64 t; cvta.to.shared.u64 t, %1; cvt.u32.u64 %0, t; }"
        : "=r"(a) : "l"(p));
    return a;
}
__device__ __forceinline__ int ldg_acq(const int* p) {
    int v;
    asm volatile("ld.global.acquire.gpu.b32 %0, [%1];" : "=r"(v) : "l"(p));
    return v;
}
__device__ __forceinline__ void ldsm4(uint32_t& r0, uint32_t& r1,
                                      uint32_t& r2, uint32_t& r3, uint32_t a) {
    asm volatile("ldmatrix.sync.aligned.m8n8.x4.shared.b16 {%0,%1,%2,%3}, [%4];"
                 : "=r"(r0), "=r"(r1), "=r"(r2), "=r"(r3) : "r"(a));
}
__device__ __forceinline__ void mma16816(float* d, const uint32_t* a,
                                         uint32_t b0, uint32_t b1) {
    asm volatile(
        "mma.sync.aligned.m16n8k16.row.col.f32.f16.f16.f32 "
        "{%0,%1,%2,%3}, {%4,%5,%6,%7}, {%8,%9}, {%0,%1,%2,%3};"
        : "+f"(d[0]), "+f"(d[1]), "+f"(d[2]), "+f"(d[3])
        : "r"(a[0]), "r"(a[1]), "r"(a[2]), "r"(a[3]), "r"(b0), "r"(b1));
}
__device__ __forceinline__ void cpa16(uint32_t dst, const void* src) {
    asm volatile("cp.async.cg.shared.global [%0], [%1], 16;"
                 :: "r"(dst), "l"(src) : "memory");
}
__device__ __forceinline__ void cpa_commit() {
    asm volatile("cp.async.commit_group;" ::: "memory");
}
template <int N>
__device__ __forceinline__ void cpa_wait() {
    asm volatile("cp.async.wait_group %0;" :: "n"(N) : "memory");
}
__device__ __forceinline__ uint32_t pack2h(float a, float b) {
    __half2 h = __floats2half2_rn(a, b);
    return *(uint32_t*)&h;
}

// ---------------------------------------------------------------------------
// reset: zero dependency flags (runs before the merged kernel each launch)
// ---------------------------------------------------------------------------
__global__ void reset_kernel()
{
    int t = threadIdx.x;
    g_flagL[t] = 0;
    if (t < 8) g_wctr[t] = 0;
}

// ---------------------------------------------------------------------------
// SMEM layout constants (fused role; ln role fits inside the same block)
// ---------------------------------------------------------------------------
constexpr int XST = 264;                        // ln role strides
constexpr int STH   = 136;                      // fused role (halves)
constexpr int B_OFF = 0;                        // [256][136]
constexpr int A_OFF = 256 * STH;                // 3 x [64][136]
constexpr int ABUF  = 64 * STH;
constexpr int G_OFF = A_OFF + 3 * ABUF;         // [128][136]
constexpr int W_OFF = G_OFF + 128 * STH;        // 2 x [128][136]
constexpr int WBUF  = 128 * STH;
constexpr int SMEM_FUSED = (W_OFF + 2 * WBUF) * 2;   // 226304 bytes

// ---------------------------------------------------------------------------
// ln role (round-14 code): LN + projections, then flag publication.
// ---------------------------------------------------------------------------
__device__ void ln_role(
    int l, const float* __restrict__ msa,
    const float* __restrict__ gamma, const float* __restrict__ beta,
    const float* __restrict__ wl, const float* __restrict__ bleft,
    const float* __restrict__ wr, const float* __restrict__ bright,
    const float* __restrict__ wo, __half* sh)
{
    __half* Xs = sh;                    // [128][264]
    __half* Wt = sh + 128 * XST;        // [64][264]
    float*  Osm = (float*)sh;           // reuse X region: [64][132]

    int tid = threadIdx.x, lane = tid & 31, w = tid >> 5;

    float4 ga0 = *(const float4*)&gamma[lane * 8];
    float4 ga1 = *(const float4*)&gamma[lane * 8 + 4];
    float4 be0 = *(const float4*)&beta[lane * 8];
    float4 be1 = *(const float4*)&beta[lane * 8 + 4];

#pragma unroll 1
    for (int rr4 = 0; rr4 < 4; rr4++) {
        float4 x0[4], x1[4];
#pragma unroll
        for (int r = 0; r < 4; r++) {
            int s = w * 16 + rr4 * 4 + r;
            const float* x = msa + ((size_t)s * L_ + l) * DM;
            x0[r] = *(const float4*)&x[lane * 8];
            x1[r] = *(const float4*)&x[lane * 8 + 4];
        }
#pragma unroll
        for (int r = 0; r < 4; r++) {
            int s = w * 16 + rr4 * 4 + r;
            float sum = x0[r].x + x0[r].y + x0[r].z + x0[r].w
                      + x1[r].x + x1[r].y + x1[r].z + x1[r].w;
            float sq  = x0[r].x*x0[r].x + x0[r].y*x0[r].y + x0[r].z*x0[r].z + x0[r].w*x0[r].w
                      + x1[r].x*x1[r].x + x1[r].y*x1[r].y + x1[r].z*x1[r].z + x1[r].w*x1[r].w;
#pragma unroll
            for (int o = 16; o > 0; o >>= 1) {
                sum += __shfl_xor_sync(0xffffffffu, sum, o);
                sq  += __shfl_xor_sync(0xffffffffu, sq,  o);
            }
            float mu = sum * (1.f / DM);
            float rstd = rsqrtf(sq * (1.f / DM) - mu * mu + 1e-5f);
            uint4 pk;
            pk.x = pack2h((x0[r].x - mu) * rstd * ga0.x + be0.x,
                          (x0[r].y - mu) * rstd * ga0.y + be0.y);
            pk.y = pack2h((x0[r].z - mu) * rstd * ga0.z + be0.z,
                          (x0[r].w - mu) * rstd * ga0.w + be0.w);
            pk.z = pack2h((x1[r].x - mu) * rstd * ga1.x + be1.x,
                          (x1[r].y - mu) * rstd * ga1.y + be1.y);
            pk.w = pack2h((x1[r].z - mu) * rstd * ga1.z + be1.z,
                          (x1[r].w - mu) * rstd * ga1.w + be1.w);
            *(uint4*)&Xs[s * XST + lane * 8] = pk;
        }
    }

    for (int e = tid; e < 8192; e += 256) {
        int d = e >> 5, h = e & 31;
        Wt[h * XST + d]        = __float2half_rn(wl[e]);
        Wt[(h + 32) * XST + d] = __float2half_rn(wr[e]);
    }
    __syncthreads();

    int wm = w >> 1, wn = w & 1;
    float acc[2][4][4];
#pragma unroll
    for (int mt = 0; mt < 2; mt++)
#pragma unroll
        for (int nt = 0; nt < 4; nt++)
#pragma unroll
            for (int q = 0; q < 4; q++) acc[mt][nt][q] = 0.f;

    uint32_t sb = smem_u32(sh);
    uint32_t aAddr = sb + (uint32_t)(((wm * 32 + (lane & 15)) * XST + (lane >> 4) * 8) * 2);
    uint32_t bAddr = sb + (uint32_t)((128 * XST
                    + (wn * 32 + ((lane >> 4) & 1) * 8 + (lane & 7)) * XST
                    + ((lane >> 3) & 1) * 8) * 2);

#pragma unroll
    for (int ks = 0; ks < 16; ks++) {
        uint32_t a[2][4], b[2][4];
#pragma unroll
        for (int mt = 0; mt < 2; mt++)
            ldsm4(a[mt][0], a[mt][1], a[mt][2], a[mt][3],
                  aAddr + (uint32_t)((mt * 16 * XST + ks * 16) * 2));
#pragma unroll
        for (int n2 = 0; n2 < 2; n2++)
            ldsm4(b[n2][0], b[n2][1], b[n2][2], b[n2][3],
                  bAddr + (uint32_t)((n2 * 16 * XST + ks * 16) * 2));
#pragma unroll
        for (int mt = 0; mt < 2; mt++)
#pragma unroll
            for (int nt = 0; nt < 4; nt++)
                mma16816(acc[mt][nt], a[mt],
                         b[nt >> 1][(nt & 1) * 2], b[nt >> 1][(nt & 1) * 2 + 1]);
    }
    __syncthreads();

    {
        int rB = lane >> 2, cB = (lane & 3) * 2;
#pragma unroll
        for (int mt = 0; mt < 2; mt++) {
            int r = wm * 32 + mt * 16 + rB;
#pragma unroll
            for (int nt = 0; nt < 4; nt++) {
                int c = wn * 32 + nt * 8 + cB;
                Osm[c * 132 + r]            = acc[mt][nt][0];
                Osm[(c + 1) * 132 + r]      = acc[mt][nt][1];
                Osm[c * 132 + r + 8]        = acc[mt][nt][2];
                Osm[(c + 1) * 132 + r + 8]  = acc[mt][nt][3];
            }
        }
    }
    __syncthreads();

    {
        int n = tid >> 2, s0 = (tid & 3) * 32;
        bool isL = n < 32;
        int hh = isL ? n : n - 32;
        float bias = isL ? bleft[hh] : bright[hh];
        float scale = isL ? 1.f : (1.f / 128.f);
        __half* dst = (isL ? g_A : g_B) + (size_t)(l * 32 + hh) * 128 + s0;
#pragma unroll
        for (int q = 0; q < 4; q++) {
            float4 v0 = *(float4*)&Osm[n * 132 + s0 + q * 8];
            float4 v1 = *(float4*)&Osm[n * 132 + s0 + q * 8 + 4];
            uint4 pk;
            pk.x = pack2h((v0.x + bias) * scale, (v0.y + bias) * scale);
            pk.y = pack2h((v0.z + bias) * scale, (v0.w + bias) * scale);
            pk.z = pack2h((v1.x + bias) * scale, (v1.y + bias) * scale);
            pk.w = pack2h((v1.z + bias) * scale, (v1.w + bias) * scale);
            *(uint4*)(dst + q * 8) = pk;
        }
    }

    // wt slice: k in [l*4, l*4+4)
#pragma unroll
    for (int it = 0; it < 2; it++) {
        int idx = l * 512 + it * 256 + tid;
        int k = idx >> 7, n = idx & 127;
        g_Wt[(size_t)n * 1024 + k] = __float2half_rn(wo[idx]);
    }

    // publish: all stores visible gpu-wide, then flags
    __threadfence();
    __syncthreads();
    if (tid == 0) {
        atomicExch(&g_flagL[l], 1);
        atomicAdd(&g_wctr[l >> 5], 1);
    }
}

// ---------------------------------------------------------------------------
// fused role (round-12/14 winner) with dependency polls.
// ---------------------------------------------------------------------------
__device__ void fused_role(
    int bl, int bm,
    const float* __restrict__ pairin,
    const float* __restrict__ bo,
    float* __restrict__ outp,
    __half* smh)
{
    float* smf = (float*)smh;
    uint32_t sb = smem_u32(smh);
    int tid = threadIdx.x, lane = tid & 31, w = tid >> 5;

    // ---- wait for A (16 l-blocks), B (8 m-blocks), W chunk 0 ----
    if (tid < 16)       { while (ldg_acq(&g_flagL[bl * 16 + tid]) == 0) {} }
    else if (tid < 24)  { while (ldg_acq(&g_flagL[bm * 8 + (tid - 16)]) == 0) {} }
    else if (tid == 24) { while (ldg_acq(&g_wctr[0]) < 32) {} }
    __syncthreads();

    const __half* gA = g_A + (size_t)(bl * 512) * 128;
    const __half* gB = g_B + (size_t)(bm * 256) * 128;

    auto prefetchW = [&](int c) {
        uint32_t base = sb + (uint32_t)((W_OFF + (c & 1) * WBUF) * 2);
        int row = tid >> 1, sg0 = (tid & 1) * 8;
        const __half* src = g_Wt + (size_t)row * 1024 + c * 128 + sg0 * 8;
        uint32_t dst = base + (uint32_t)((row * STH + sg0 * 8) * 2);
#pragma unroll
        for (int sg = 0; sg < 8; sg++) cpa16(dst + sg * 16, src + sg * 8);
    };
    auto prefetchA = [&](int c) {
        uint32_t base = sb + (uint32_t)((A_OFF + (c % 3) * ABUF) * 2);
#pragma unroll
        for (int it = 0; it < 4; it++) {
            int f = it * 256 + tid;
            int r = f >> 4, c8 = (f & 15) * 8;
            int grow = (r >> 2) * 32 + c * 4 + (r & 3);
            cpa16(base + (uint32_t)((r * STH + c8) * 2),
                  gA + (size_t)grow * 128 + c8);
        }
    };

#pragma unroll
    for (int it = 0; it < 16; it++) {
        int f = it * 256 + tid;
        int r = f >> 4, c8 = (f & 15) * 8;
        cpa16(sb + (uint32_t)((B_OFF + r * STH + c8) * 2),
              gB + (size_t)r * 128 + c8);
    }
    prefetchA(0);
    prefetchA(1);
    prefetchW(0);
    cpa_commit();

    float outAcc[4][4][4];
#pragma unroll
    for (int mt = 0; mt < 4; mt++)
#pragma unroll
        for (int nt = 0; nt < 4; nt++)
#pragma unroll
            for (int q = 0; q < 4; q++) outAcc[mt][nt][q] = 0.f;

    int wm2 = w >> 2;
    int wn4 = w & 3;
    int wmB = w >> 2, wnB = w & 3;

    uint32_t aAddrA0 = sb + (uint32_t)((A_OFF + (wm2 * 32 + (lane & 15)) * STH
                                        + (lane >> 4) * 8) * 2);
    uint32_t bAddrA  = sb + (uint32_t)((B_OFF + (wn4 * 64 + ((lane >> 4) & 1) * 8 + (lane & 7)) * STH
                                        + ((lane >> 3) & 1) * 8) * 2);
    uint32_t aAddrB  = sb + (uint32_t)((G_OFF + (wmB * 64 + (lane & 15)) * STH
                                        + (lane >> 4) * 8) * 2);
    uint32_t bAddrW0 = (uint32_t)((W_OFF + (wnB * 32 + ((lane >> 4) & 1) * 8 + (lane & 7)) * STH
                                   + ((lane >> 3) & 1) * 8) * 2);

    cpa_wait<0>();
    __syncthreads();

#pragma unroll 1
    for (int ic = 0; ic < 8; ic++) {
        if (ic > 0) __syncthreads();
        if (ic < 6) prefetchA(ic + 2);
        if (ic < 7) {
            // W chunk ic+1 needs ln group (ic+1) complete (all threads poll;
            // flag is L2-resident and normally already set)
            while (ldg_acq(&g_wctr[ic + 1]) < 32) {}
            prefetchW(ic + 1);
            cpa_commit();
        }

        uint32_t aA = aAddrA0 + (uint32_t)((ic % 3) * ABUF * 2);
        float accA[2][8][4];
#pragma unroll
        for (int mt = 0; mt < 2; mt++)
#pragma unroll
            for (int nt = 0; nt < 8; nt++)
#pragma unroll
                for (int q = 0; q < 4; q++) accA[mt][nt][q] = 0.f;

#pragma unroll
        for (int ks = 0; ks < 8; ks++) {
            uint32_t a[2][4], b[4][4];
#pragma unroll
            for (int mt = 0; mt < 2; mt++)
                ldsm4(a[mt][0], a[mt][1], a[mt][2], a[mt][3],
                      aA + (uint32_t)((mt * 16 * STH + ks * 16) * 2));
#pragma unroll
            for (int pr = 0; pr < 4; pr++)
                ldsm4(b[pr][0], b[pr][1], b[pr][2], b[pr][3],
                      bAddrA + (uint32_t)((pr * 16 * STH + ks * 16) * 2));
#pragma unroll
            for (int mt = 0; mt < 2; mt++)
#pragma unroll
                for (int nt = 0; nt < 8; nt++)
                    mma16816(accA[mt][nt], a[mt],
                             b[nt >> 1][(nt & 1) * 2], b[nt >> 1][(nt & 1) * 2 + 1]);
        }

        {
            int rq = lane >> 2, cq = (lane & 3) * 2;
#pragma unroll
            for (int mt = 0; mt < 2; mt++) {
#pragma unroll
                for (int nt = 0; nt < 8; nt++) {
                    int cc = wn4 * 64 + nt * 8 + cq;
                    int mloc = cc >> 5, jj = cc & 31;
#pragma unroll
                    for (int rh = 0; rh < 2; rh++) {
                        int r = wm2 * 32 + mt * 16 + rh * 8 + rq;
                        int p = (r >> 2) * 8 + mloc;
                        int col = (r & 3) * 32 + jj;
                        *(uint32_t*)(smh + G_OFF + p * STH + col) =
                            pack2h(accA[mt][nt][rh * 2], accA[mt][nt][rh * 2 + 1]);
                    }
                }
            }
        }
        if (ic < 7) { cpa_wait<1>(); } else { cpa_wait<0>(); }
        __syncthreads();

        uint32_t sW = sb + bAddrW0 + (uint32_t)((ic & 1) * WBUF * 2);
#pragma unroll
        for (int ks = 0; ks < 8; ks++) {
            uint32_t a[4][4], b[2][4];
#pragma unroll
            for (int mt = 0; mt < 4; mt++)
                ldsm4(a[mt][0], a[mt][1], a[mt][2], a[mt][3],
                      aAddrB + (uint32_t)((mt * 16 * STH + ks * 16) * 2));
#pragma unroll
            for (int pr = 0; pr < 2; pr++)
                ldsm4(b[pr][0], b[pr][1], b[pr][2], b[pr][3],
                      sW + (uint32_t)((pr * 16 * STH + ks * 16) * 2));
#pragma unroll
            for (int mt = 0; mt < 4; mt++)
#pragma unroll
                for (int nt = 0; nt < 4; nt++)
                    mma16816(outAcc[mt][nt], a[mt],
                             b[nt >> 1][(nt & 1) * 2], b[nt >> 1][(nt & 1) * 2 + 1]);
        }
    }
    __syncthreads();

    {
        int rB = lane >> 2, nB = (lane & 3) * 2;
#pragma unroll
        for (int mt = 0; mt < 4; mt++) {
            int p = wmB * 64 + mt * 16 + rB;
#pragma unroll
            for (int nt = 0; nt < 4; nt++) {
                int nc = wnB * 32 + nt * 8 + nB;
                *(float2*)&smf[p * 132 + nc] =
                    make_float2(outAcc[mt][nt][0], outAcc[mt][nt][1]);
                *(float2*)&smf[(p + 8) * 132 + nc] =
                    make_float2(outAcc[mt][nt][2], outAcc[mt][nt][3]);
            }
        }
    }
    __syncthreads();

#pragma unroll
    for (int it = 0; it < 16; it++) {
        int f = it * 256 + tid;
        int p = f >> 5;
        int c4 = (f & 31) * 4;
        int l = bl * 16 + (p >> 3);
        int m = bm * 8 + (p & 7);
        size_t o = ((size_t)(l * L_ + m)) * DP + c4;
        float4 v = *(float4*)&smf[p * 132 + c4];
        float4 pv = *(const float4*)&pairin[o];
        float4 bv = *(const float4*)&bo[c4];
        v.x += pv.x + bv.x; v.y += pv.y + bv.y;
        v.z += pv.z + bv.z; v.w += pv.w + bv.w;
        *(float4*)&outp[o] = v;
    }
}

// ---------------------------------------------------------------------------
// merged kernel: blocks 0..255 = ln role; 256..767 = fused role
// ---------------------------------------------------------------------------
__global__ void __launch_bounds__(256, 1) merged_kernel(
    const float* __restrict__ msa,
    const float* __restrict__ pairin,
    const float* __restrict__ gamma,
    const float* __restrict__ beta,
    const float* __restrict__ wl,
    const float* __restrict__ bleft,
    const float* __restrict__ wr,
    const float* __restrict__ bright,
    const float* __restrict__ wo,
    const float* __restrict__ bo,
    float* __restrict__ outp)
{
    extern __shared__ __half sh[];
    int b = blockIdx.x;
    if (b < 256) {
        ln_role(b, msa, gamma, beta, wl, bleft, wr, bright, wo, sh);
    } else {
        int fid = b - 256;
        fused_role(fid >> 5, fid & 31, pairin, bo, outp, sh);
    }
}

// ---------------------------------------------------------------------------
// Launch
// ---------------------------------------------------------------------------
extern "C" void kernel_launch(void* const* d_in, const int* in_sizes, int n_in,
                              void* d_out, int out_size)
{
    const float* msa    = (const float*)d_in[0];
    const float* pairin = (const float*)d_in[1];
    const float* gamma  = (const float*)d_in[4];
    const float* beta   = (const float*)d_in[5];
    const float* wl     = (const float*)d_in[6];
    const float* bleft  = (const float*)d_in[7];
    const float* wr     = (const float*)d_in[8];
    const float* bright = (const float*)d_in[9];
    const float* wo     = (const float*)d_in[10];
    const float* bo     = (const float*)d_in[11];
    float* outp = (float*)d_out;

    cudaFuncSetAttribute(merged_kernel,
                         cudaFuncAttributeMaxDynamicSharedMemorySize, SMEM_FUSED);

    reset_kernel<<<1, 256>>>();
    merged_kernel<<<768, 256, SMEM_FUSED>>>(msa, pairin, gamma, beta,
                                            wl, bleft, wr, bright, wo, bo, outp);
}

// round 16
// speedup vs baseline: 1.1163x; 1.1163x over previous
#include <cuda_runtime.h>
#include <cuda_fp16.h>
#include <cstdint>

// Shapes (fixed)
constexpr int N_  = 128;
constexpr int L_  = 256;
constexpr int DM  = 256;
constexpr int DP  = 128;

// Device scratch (fp16)
__device__ __half g_A[8192 * 128];   // [(l*32+i)][s]
__device__ __half g_B[8192 * 128];   // [(m*32+j)][s]
__device__ __half g_Wt[DP * 1024];   // [n][ij]

// ---------------------------------------------------------------------------
// helpers
// ---------------------------------------------------------------------------
__device__ __forceinline__ uint32_t smem_u32(const void* p) {
    uint32_t a;
    asm("{ .reg .u64 t; cvta.to.shared.u64 t, %1; cvt.u32.u64 %0, t; }"
        : "=r"(a) : "l"(p));
    return a;
}
__device__ __forceinline__ void ldsm4(uint32_t& r0, uint32_t& r1,
                                      uint32_t& r2, uint32_t& r3, uint32_t a) {
    asm volatile("ldmatrix.sync.aligned.m8n8.x4.shared.b16 {%0,%1,%2,%3}, [%4];"
                 : "=r"(r0), "=r"(r1), "=r"(r2), "=r"(r3) : "r"(a));
}
__device__ __forceinline__ void mma16816(float* d, const uint32_t* a,
                                         uint32_t b0, uint32_t b1) {
    asm volatile(
        "mma.sync.aligned.m16n8k16.row.col.f32.f16.f16.f32 "
        "{%0,%1,%2,%3}, {%4,%5,%6,%7}, {%8,%9}, {%0,%1,%2,%3};"
        : "+f"(d[0]), "+f"(d[1]), "+f"(d[2]), "+f"(d[3])
        : "r"(a[0]), "r"(a[1]), "r"(a[2]), "r"(a[3]), "r"(b0), "r"(b1));
}
// f16-accumulate variant (D,C packed half2 x2)
__device__ __forceinline__ void mma16816h(uint32_t* d, const uint32_t* a,
                                          uint32_t b0, uint32_t b1) {
    asm volatile(
        "mma.sync.aligned.m16n8k16.row.col.f16.f16.f16.f16 "
        "{%0,%1}, {%2,%3,%4,%5}, {%6,%7}, {%0,%1};"
        : "+r"(d[0]), "+r"(d[1])
        : "r"(a[0]), "r"(a[1]), "r"(a[2]), "r"(a[3]), "r"(b0), "r"(b1));
}
__device__ __forceinline__ void cpa16(uint32_t dst, const void* src) {
    asm volatile("cp.async.cg.shared.global [%0], [%1], 16;"
                 :: "r"(dst), "l"(src) : "memory");
}
__device__ __forceinline__ void cpa_commit() {
    asm volatile("cp.async.commit_group;" ::: "memory");
}
template <int N>
__device__ __forceinline__ void cpa_wait() {
    asm volatile("cp.async.wait_group %0;" :: "n"(N) : "memory");
}
__device__ __forceinline__ uint32_t pack2h(float a, float b) {
    __half2 h = __floats2half2_rn(a, b);
    return *(uint32_t*)&h;
}

// ---------------------------------------------------------------------------
// Kernel 1: LN + projections via tensor cores (round-14 version, unchanged).
// ---------------------------------------------------------------------------
constexpr int XST = 264;

__global__ void __launch_bounds__(256) ln_proj_kernel(
    const float* __restrict__ msa,
    const float* __restrict__ gamma,
    const float* __restrict__ beta,
    const float* __restrict__ wl,
    const float* __restrict__ bleft,
    const float* __restrict__ wr,
    const float* __restrict__ bright,
    const float* __restrict__ wo)
{
    extern __shared__ __half sh[];
    __half* Xs = sh;                    // [128][264]
    __half* Wt = sh + 128 * XST;        // [64][264]
    float*  Osm = (float*)sh;           // reuse X region: [64][132]

    int tid = threadIdx.x, lane = tid & 31, w = tid >> 5;
    int l = blockIdx.x;

    float4 ga0 = *(const float4*)&gamma[lane * 8];
    float4 ga1 = *(const float4*)&gamma[lane * 8 + 4];
    float4 be0 = *(const float4*)&beta[lane * 8];
    float4 be1 = *(const float4*)&beta[lane * 8 + 4];

#pragma unroll 1
    for (int rr4 = 0; rr4 < 4; rr4++) {
        float4 x0[4], x1[4];
#pragma unroll
        for (int r = 0; r < 4; r++) {
            int s = w * 16 + rr4 * 4 + r;
            const float* x = msa + ((size_t)s * L_ + l) * DM;
            x0[r] = *(const float4*)&x[lane * 8];
            x1[r] = *(const float4*)&x[lane * 8 + 4];
        }
#pragma unroll
        for (int r = 0; r < 4; r++) {
            int s = w * 16 + rr4 * 4 + r;
            float sum = x0[r].x + x0[r].y + x0[r].z + x0[r].w
                      + x1[r].x + x1[r].y + x1[r].z + x1[r].w;
            float sq  = x0[r].x*x0[r].x + x0[r].y*x0[r].y + x0[r].z*x0[r].z + x0[r].w*x0[r].w
                      + x1[r].x*x1[r].x + x1[r].y*x1[r].y + x1[r].z*x1[r].z + x1[r].w*x1[r].w;
#pragma unroll
            for (int o = 16; o > 0; o >>= 1) {
                sum += __shfl_xor_sync(0xffffffffu, sum, o);
                sq  += __shfl_xor_sync(0xffffffffu, sq,  o);
            }
            float mu = sum * (1.f / DM);
            float rstd = rsqrtf(sq * (1.f / DM) - mu * mu + 1e-5f);
            uint4 pk;
            pk.x = pack2h((x0[r].x - mu) * rstd * ga0.x + be0.x,
                          (x0[r].y - mu) * rstd * ga0.y + be0.y);
            pk.y = pack2h((x0[r].z - mu) * rstd * ga0.z + be0.z,
                          (x0[r].w - mu) * rstd * ga0.w + be0.w);
            pk.z = pack2h((x1[r].x - mu) * rstd * ga1.x + be1.x,
                          (x1[r].y - mu) * rstd * ga1.y + be1.y);
            pk.w = pack2h((x1[r].z - mu) * rstd * ga1.z + be1.z,
                          (x1[r].w - mu) * rstd * ga1.w + be1.w);
            *(uint4*)&Xs[s * XST + lane * 8] = pk;
        }
    }

    for (int e = tid; e < 8192; e += 256) {
        int d = e >> 5, h = e & 31;
        Wt[h * XST + d]        = __float2half_rn(wl[e]);
        Wt[(h + 32) * XST + d] = __float2half_rn(wr[e]);
    }
    __syncthreads();

    int wm = w >> 1, wn = w & 1;
    float acc[2][4][4];
#pragma unroll
    for (int mt = 0; mt < 2; mt++)
#pragma unroll
        for (int nt = 0; nt < 4; nt++)
#pragma unroll
            for (int q = 0; q < 4; q++) acc[mt][nt][q] = 0.f;

    uint32_t sb = smem_u32(sh);
    uint32_t aAddr = sb + (uint32_t)(((wm * 32 + (lane & 15)) * XST + (lane >> 4) * 8) * 2);
    uint32_t bAddr = sb + (uint32_t)((128 * XST
                    + (wn * 32 + ((lane >> 4) & 1) * 8 + (lane & 7)) * XST
                    + ((lane >> 3) & 1) * 8) * 2);

#pragma unroll
    for (int ks = 0; ks < 16; ks++) {
        uint32_t a[2][4], b[2][4];
#pragma unroll
        for (int mt = 0; mt < 2; mt++)
            ldsm4(a[mt][0], a[mt][1], a[mt][2], a[mt][3],
                  aAddr + (uint32_t)((mt * 16 * XST + ks * 16) * 2));
#pragma unroll
        for (int n2 = 0; n2 < 2; n2++)
            ldsm4(b[n2][0], b[n2][1], b[n2][2], b[n2][3],
                  bAddr + (uint32_t)((n2 * 16 * XST + ks * 16) * 2));
#pragma unroll
        for (int mt = 0; mt < 2; mt++)
#pragma unroll
            for (int nt = 0; nt < 4; nt++)
                mma16816(acc[mt][nt], a[mt],
                         b[nt >> 1][(nt & 1) * 2], b[nt >> 1][(nt & 1) * 2 + 1]);
    }
    __syncthreads();

    {
        int rB = lane >> 2, cB = (lane & 3) * 2;
#pragma unroll
        for (int mt = 0; mt < 2; mt++) {
            int r = wm * 32 + mt * 16 + rB;
#pragma unroll
            for (int nt = 0; nt < 4; nt++) {
                int c = wn * 32 + nt * 8 + cB;
                Osm[c * 132 + r]            = acc[mt][nt][0];
                Osm[(c + 1) * 132 + r]      = acc[mt][nt][1];
                Osm[c * 132 + r + 8]        = acc[mt][nt][2];
                Osm[(c + 1) * 132 + r + 8]  = acc[mt][nt][3];
            }
        }
    }
    __syncthreads();

    {
        int n = tid >> 2, s0 = (tid & 3) * 32;
        bool isL = n < 32;
        int hh = isL ? n : n - 32;
        float bias = isL ? bleft[hh] : bright[hh];
        float scale = isL ? 1.f : (1.f / 128.f);
        __half* dst = (isL ? g_A : g_B) + (size_t)(l * 32 + hh) * 128 + s0;
#pragma unroll
        for (int q = 0; q < 4; q++) {
            float4 v0 = *(float4*)&Osm[n * 132 + s0 + q * 8];
            float4 v1 = *(float4*)&Osm[n * 132 + s0 + q * 8 + 4];
            uint4 pk;
            pk.x = pack2h((v0.x + bias) * scale, (v0.y + bias) * scale);
            pk.y = pack2h((v0.z + bias) * scale, (v0.w + bias) * scale);
            pk.z = pack2h((v1.x + bias) * scale, (v1.y + bias) * scale);
            pk.w = pack2h((v1.z + bias) * scale, (v1.w + bias) * scale);
            *(uint4*)(dst + q * 8) = pk;
        }
    }

#pragma unroll
    for (int it = 0; it < 2; it++) {
        int idx = blockIdx.x * 512 + it * 256 + tid;
        int k = idx >> 7, n = idx & 127;
        g_Wt[(size_t)n * 1024 + k] = __float2half_rn(wo[idx]);
    }
}

// ---------------------------------------------------------------------------
// Fused GEMM (round-14 structure; phase A switched to f16-accumulate HMMA).
// CTA = 16 l x 8 m, grid (16,32).
// ---------------------------------------------------------------------------
constexpr int STH   = 136;                      // halves
constexpr int B_OFF = 0;                        // [256][136]
constexpr int A_OFF = 256 * STH;                // 3 x [64][136]
constexpr int ABUF  = 64 * STH;
constexpr int G_OFF = A_OFF + 3 * ABUF;         // [128][136]
constexpr int W_OFF = G_OFF + 128 * STH;        // 2 x [128][136]
constexpr int WBUF  = 128 * STH;
constexpr int SMEM_FUSED = (W_OFF + 2 * WBUF) * 2;   // 226304 bytes

__global__ void __launch_bounds__(256, 1) fused_gemm_kernel(
    const float* __restrict__ pairin,
    const float* __restrict__ bo,
    float* __restrict__ outp)
{
    extern __shared__ __half smh[];
    float* smf = (float*)smh;
    uint32_t sb = smem_u32(smh);
    int tid = threadIdx.x, lane = tid & 31, w = tid >> 5;
    int bl = blockIdx.x, bm = blockIdx.y;

    const __half* gA = g_A + (size_t)(bl * 512) * 128;
    const __half* gB = g_B + (size_t)(bm * 256) * 128;

    auto prefetchW = [&](int c) {
        uint32_t base = sb + (uint32_t)((W_OFF + (c & 1) * WBUF) * 2);
        int row = tid >> 1, sg0 = (tid & 1) * 8;
        const __half* src = g_Wt + (size_t)row * 1024 + c * 128 + sg0 * 8;
        uint32_t dst = base + (uint32_t)((row * STH + sg0 * 8) * 2);
#pragma unroll
        for (int sg = 0; sg < 8; sg++) cpa16(dst + sg * 16, src + sg * 8);
    };
    auto prefetchA = [&](int c) {
        uint32_t base = sb + (uint32_t)((A_OFF + (c % 3) * ABUF) * 2);
#pragma unroll
        for (int it = 0; it < 4; it++) {
            int f = it * 256 + tid;
            int r = f >> 4, c8 = (f & 15) * 8;
            int grow = (r >> 2) * 32 + c * 4 + (r & 3);
            cpa16(base + (uint32_t)((r * STH + c8) * 2),
                  gA + (size_t)grow * 128 + c8);
        }
    };

#pragma unroll
    for (int it = 0; it < 16; it++) {
        int f = it * 256 + tid;
        int r = f >> 4, c8 = (f & 15) * 8;
        cpa16(sb + (uint32_t)((B_OFF + r * STH + c8) * 2),
              gB + (size_t)r * 128 + c8);
    }
    prefetchA(0);
    prefetchA(1);
    prefetchW(0);
    cpa_commit();

    float outAcc[4][4][4];
#pragma unroll
    for (int mt = 0; mt < 4; mt++)
#pragma unroll
        for (int nt = 0; nt < 4; nt++)
#pragma unroll
            for (int q = 0; q < 4; q++) outAcc[mt][nt][q] = 0.f;

    int wm2 = w >> 2;
    int wn4 = w & 3;
    int wmB = w >> 2, wnB = w & 3;

    uint32_t aAddrA0 = sb + (uint32_t)((A_OFF + (wm2 * 32 + (lane & 15)) * STH
                                        + (lane >> 4) * 8) * 2);
    uint32_t bAddrA  = sb + (uint32_t)((B_OFF + (wn4 * 64 + ((lane >> 4) & 1) * 8 + (lane & 7)) * STH
                                        + ((lane >> 3) & 1) * 8) * 2);
    uint32_t aAddrB  = sb + (uint32_t)((G_OFF + (wmB * 64 + (lane & 15)) * STH
                                        + (lane >> 4) * 8) * 2);
    uint32_t bAddrW0 = (uint32_t)((W_OFF + (wnB * 32 + ((lane >> 4) & 1) * 8 + (lane & 7)) * STH
                                   + ((lane >> 3) & 1) * 8) * 2);

    cpa_wait<0>();
    __syncthreads();

#pragma unroll 1
    for (int ic = 0; ic < 8; ic++) {
        if (ic > 0) __syncthreads();
        if (ic < 6) prefetchA(ic + 2);
        if (ic < 7) { prefetchW(ic + 1); cpa_commit(); }

        // ---- phase A: D[64 A-rows x 256 m-rows], K=128 s, f16 accum ----
        uint32_t aA = aAddrA0 + (uint32_t)((ic % 3) * ABUF * 2);
        uint32_t accA[2][8][2];
#pragma unroll
        for (int mt = 0; mt < 2; mt++)
#pragma unroll
            for (int nt = 0; nt < 8; nt++) {
                accA[mt][nt][0] = 0u; accA[mt][nt][1] = 0u;
            }

#pragma unroll
        for (int ks = 0; ks < 8; ks++) {
            uint32_t a[2][4], b[4][4];
#pragma unroll
            for (int mt = 0; mt < 2; mt++)
                ldsm4(a[mt][0], a[mt][1], a[mt][2], a[mt][3],
                      aA + (uint32_t)((mt * 16 * STH + ks * 16) * 2));
#pragma unroll
            for (int pr = 0; pr < 4; pr++)
                ldsm4(b[pr][0], b[pr][1], b[pr][2], b[pr][3],
                      bAddrA + (uint32_t)((pr * 16 * STH + ks * 16) * 2));
#pragma unroll
            for (int mt = 0; mt < 2; mt++)
#pragma unroll
                for (int nt = 0; nt < 8; nt++)
                    mma16816h(accA[mt][nt], a[mt],
                              b[nt >> 1][(nt & 1) * 2], b[nt >> 1][(nt & 1) * 2 + 1]);
        }

        // ---- scatter accA -> Gs[pair][ij_local] (direct half2 reg stores) ----
        {
            int rq = lane >> 2, cq = (lane & 3) * 2;
#pragma unroll
            for (int mt = 0; mt < 2; mt++) {
#pragma unroll
                for (int nt = 0; nt < 8; nt++) {
                    int cc = wn4 * 64 + nt * 8 + cq;
                    int mloc = cc >> 5, jj = cc & 31;
#pragma unroll
                    for (int rh = 0; rh < 2; rh++) {
                        int r = wm2 * 32 + mt * 16 + rh * 8 + rq;
                        int p = (r >> 2) * 8 + mloc;
                        int col = (r & 3) * 32 + jj;
                        *(uint32_t*)(smh + G_OFF + p * STH + col) = accA[mt][nt][rh];
                    }
                }
            }
        }
        if (ic < 7) { cpa_wait<1>(); } else { cpa_wait<0>(); }
        __syncthreads();

        // ---- phase B: out += Gs @ W[ic]^T (f32 accum) ----
        uint32_t sW = sb + bAddrW0 + (uint32_t)((ic & 1) * WBUF * 2);
#pragma unroll
        for (int ks = 0; ks < 8; ks++) {
            uint32_t a[4][4], b[2][4];
#pragma unroll
            for (int mt = 0; mt < 4; mt++)
                ldsm4(a[mt][0], a[mt][1], a[mt][2], a[mt][3],
                      aAddrB + (uint32_t)((mt * 16 * STH + ks * 16) * 2));
#pragma unroll
            for (int pr = 0; pr < 2; pr++)
                ldsm4(b[pr][0], b[pr][1], b[pr][2], b[pr][3],
                      sW + (uint32_t)((pr * 16 * STH + ks * 16) * 2));
#pragma unroll
            for (int mt = 0; mt < 4; mt++)
#pragma unroll
                for (int nt = 0; nt < 4; nt++)
                    mma16816(outAcc[mt][nt], a[mt],
                             b[nt >> 1][(nt & 1) * 2], b[nt >> 1][(nt & 1) * 2 + 1]);
        }
    }
    __syncthreads();

    {
        int rB = lane >> 2, nB = (lane & 3) * 2;
#pragma unroll
        for (int mt = 0; mt < 4; mt++) {
            int p = wmB * 64 + mt * 16 + rB;
#pragma unroll
            for (int nt = 0; nt < 4; nt++) {
                int nc = wnB * 32 + nt * 8 + nB;
                *(float2*)&smf[p * 132 + nc] =
                    make_float2(outAcc[mt][nt][0], outAcc[mt][nt][1]);
                *(float2*)&smf[(p + 8) * 132 + nc] =
                    make_float2(outAcc[mt][nt][2], outAcc[mt][nt][3]);
            }
        }
    }
    __syncthreads();

#pragma unroll
    for (int it = 0; it < 16; it++) {
        int f = it * 256 + tid;
        int p = f >> 5;
        int c4 = (f & 31) * 4;
        int l = bl * 16 + (p >> 3);
        int m = bm * 8 + (p & 7);
        size_t o = ((size_t)(l * L_ + m)) * DP + c4;
        float4 v = *(float4*)&smf[p * 132 + c4];
        float4 pv = *(const float4*)&pairin[o];
        float4 bv = *(const float4*)&bo[c4];
        v.x += pv.x + bv.x; v.y += pv.y + bv.y;
        v.z += pv.z + bv.z; v.w += pv.w + bv.w;
        *(float4*)&outp[o] = v;
    }
}

// ---------------------------------------------------------------------------
// Launch
// ---------------------------------------------------------------------------
extern "C" void kernel_launch(void* const* d_in, const int* in_sizes, int n_in,
                              void* d_out, int out_size)
{
    const float* msa    = (const float*)d_in[0];
    const float* pairin = (const float*)d_in[1];
    const float* gamma  = (const float*)d_in[4];
    const float* beta   = (const float*)d_in[5];
    const float* wl     = (const float*)d_in[6];
    const float* bleft  = (const float*)d_in[7];
    const float* wr     = (const float*)d_in[8];
    const float* bright = (const float*)d_in[9];
    const float* wo     = (const float*)d_in[10];
    const float* bo     = (const float*)d_in[11];
    float* outp = (float*)d_out;

    int smemLn = 192 * XST * 2;   // 101376 bytes
    cudaFuncSetAttribute(ln_proj_kernel,
                         cudaFuncAttributeMaxDynamicSharedMemorySize, smemLn);
    cudaFuncSetAttribute(fused_gemm_kernel,
                         cudaFuncAttributeMaxDynamicSharedMemorySize, SMEM_FUSED);

    ln_proj_kernel<<<256, 256, smemLn>>>(msa, gamma, beta, wl, bleft, wr, bright, wo);
    fused_gemm_kernel<<<dim3(16, 32), 256, SMEM_FUSED>>>(pairin, bo, outp);
}

// round 17
// speedup vs baseline: 1.1172x; 1.0008x over previous
#include <cuda_runtime.h>
#include <cuda_fp16.h>
#include <cstdint>

// Shapes (fixed)
constexpr int N_  = 128;
constexpr int L_  = 256;
constexpr int DM  = 256;
constexpr int DP  = 128;

// Device scratch (fp16)
__device__ __half g_A[8192 * 128];   // [(l*32+i)][s]
__device__ __half g_B[8192 * 128];   // [(m*32+j)][s]
__device__ __half g_Wt[DP * 1024];   // [n][ij]

// ---------------------------------------------------------------------------
// helpers
// ---------------------------------------------------------------------------
__device__ __forceinline__ uint32_t smem_u32(const void* p) {
    uint32_t a;
    asm("{ .reg .u64 t; cvta.to.shared.u64 t, %1; cvt.u32.u64 %0, t; }"
        : "=r"(a) : "l"(p));
    return a;
}
__device__ __forceinline__ void ldsm4(uint32_t& r0, uint32_t& r1,
                                      uint32_t& r2, uint32_t& r3, uint32_t a) {
    asm volatile("ldmatrix.sync.aligned.m8n8.x4.shared.b16 {%0,%1,%2,%3}, [%4];"
                 : "=r"(r0), "=r"(r1), "=r"(r2), "=r"(r3) : "r"(a));
}
__device__ __forceinline__ void mma16816(float* d, const uint32_t* a,
                                         uint32_t b0, uint32_t b1) {
    asm volatile(
        "mma.sync.aligned.m16n8k16.row.col.f32.f16.f16.f32 "
        "{%0,%1,%2,%3}, {%4,%5,%6,%7}, {%8,%9}, {%0,%1,%2,%3};"
        : "+f"(d[0]), "+f"(d[1]), "+f"(d[2]), "+f"(d[3])
        : "r"(a[0]), "r"(a[1]), "r"(a[2]), "r"(a[3]), "r"(b0), "r"(b1));
}
__device__ __forceinline__ void mma16816h(uint32_t* d, const uint32_t* a,
                                          uint32_t b0, uint32_t b1) {
    asm volatile(
        "mma.sync.aligned.m16n8k16.row.col.f16.f16.f16.f16 "
        "{%0,%1}, {%2,%3,%4,%5}, {%6,%7}, {%0,%1};"
        : "+r"(d[0]), "+r"(d[1])
        : "r"(a[0]), "r"(a[1]), "r"(a[2]), "r"(a[3]), "r"(b0), "r"(b1));
}
__device__ __forceinline__ void cpa16(uint32_t dst, const void* src) {
    asm volatile("cp.async.cg.shared.global [%0], [%1], 16;"
                 :: "r"(dst), "l"(src) : "memory");
}
__device__ __forceinline__ void cpa_commit() {
    asm volatile("cp.async.commit_group;" ::: "memory");
}
template <int N>
__device__ __forceinline__ void cpa_wait() {
    asm volatile("cp.async.wait_group %0;" :: "n"(N) : "memory");
}
__device__ __forceinline__ uint32_t pack2h(float a, float b) {
    __half2 h = __floats2half2_rn(a, b);
    return *(uint32_t*)&h;
}

// ---------------------------------------------------------------------------
// Kernel 1: LN + projections via tensor cores (round-16 version, unchanged).
// ---------------------------------------------------------------------------
constexpr int XST = 264;

__global__ void __launch_bounds__(256) ln_proj_kernel(
    const float* __restrict__ msa,
    const float* __restrict__ gamma,
    const float* __restrict__ beta,
    const float* __restrict__ wl,
    const float* __restrict__ bleft,
    const float* __restrict__ wr,
    const float* __restrict__ bright,
    const float* __restrict__ wo)
{
    extern __shared__ __half sh[];
    __half* Xs = sh;                    // [128][264]
    __half* Wt = sh + 128 * XST;        // [64][264]
    float*  Osm = (float*)sh;           // reuse X region: [64][132]

    int tid = threadIdx.x, lane = tid & 31, w = tid >> 5;
    int l = blockIdx.x;

    float4 ga0 = *(const float4*)&gamma[lane * 8];
    float4 ga1 = *(const float4*)&gamma[lane * 8 + 4];
    float4 be0 = *(const float4*)&beta[lane * 8];
    float4 be1 = *(const float4*)&beta[lane * 8 + 4];

#pragma unroll 1
    for (int rr4 = 0; rr4 < 4; rr4++) {
        float4 x0[4], x1[4];
#pragma unroll
        for (int r = 0; r < 4; r++) {
            int s = w * 16 + rr4 * 4 + r;
            const float* x = msa + ((size_t)s * L_ + l) * DM;
            x0[r] = *(const float4*)&x[lane * 8];
            x1[r] = *(const float4*)&x[lane * 8 + 4];
        }
#pragma unroll
        for (int r = 0; r < 4; r++) {
            int s = w * 16 + rr4 * 4 + r;
            float sum = x0[r].x + x0[r].y + x0[r].z + x0[r].w
                      + x1[r].x + x1[r].y + x1[r].z + x1[r].w;
            float sq  = x0[r].x*x0[r].x + x0[r].y*x0[r].y + x0[r].z*x0[r].z + x0[r].w*x0[r].w
                      + x1[r].x*x1[r].x + x1[r].y*x1[r].y + x1[r].z*x1[r].z + x1[r].w*x1[r].w;
#pragma unroll
            for (int o = 16; o > 0; o >>= 1) {
                sum += __shfl_xor_sync(0xffffffffu, sum, o);
                sq  += __shfl_xor_sync(0xffffffffu, sq,  o);
            }
            float mu = sum * (1.f / DM);
            float rstd = rsqrtf(sq * (1.f / DM) - mu * mu + 1e-5f);
            uint4 pk;
            pk.x = pack2h((x0[r].x - mu) * rstd * ga0.x + be0.x,
                          (x0[r].y - mu) * rstd * ga0.y + be0.y);
            pk.y = pack2h((x0[r].z - mu) * rstd * ga0.z + be0.z,
                          (x0[r].w - mu) * rstd * ga0.w + be0.w);
            pk.z = pack2h((x1[r].x - mu) * rstd * ga1.x + be1.x,
                          (x1[r].y - mu) * rstd * ga1.y + be1.y);
            pk.w = pack2h((x1[r].z - mu) * rstd * ga1.z + be1.z,
                          (x1[r].w - mu) * rstd * ga1.w + be1.w);
            *(uint4*)&Xs[s * XST + lane * 8] = pk;
        }
    }

    for (int e = tid; e < 8192; e += 256) {
        int d = e >> 5, h = e & 31;
        Wt[h * XST + d]        = __float2half_rn(wl[e]);
        Wt[(h + 32) * XST + d] = __float2half_rn(wr[e]);
    }
    __syncthreads();

    int wm = w >> 1, wn = w & 1;
    float acc[2][4][4];
#pragma unroll
    for (int mt = 0; mt < 2; mt++)
#pragma unroll
        for (int nt = 0; nt < 4; nt++)
#pragma unroll
            for (int q = 0; q < 4; q++) acc[mt][nt][q] = 0.f;

    uint32_t sb = smem_u32(sh);
    uint32_t aAddr = sb + (uint32_t)(((wm * 32 + (lane & 15)) * XST + (lane >> 4) * 8) * 2);
    uint32_t bAddr = sb + (uint32_t)((128 * XST
                    + (wn * 32 + ((lane >> 4) & 1) * 8 + (lane & 7)) * XST
                    + ((lane >> 3) & 1) * 8) * 2);

#pragma unroll
    for (int ks = 0; ks < 16; ks++) {
        uint32_t a[2][4], b[2][4];
#pragma unroll
        for (int mt = 0; mt < 2; mt++)
            ldsm4(a[mt][0], a[mt][1], a[mt][2], a[mt][3],
                  aAddr + (uint32_t)((mt * 16 * XST + ks * 16) * 2));
#pragma unroll
        for (int n2 = 0; n2 < 2; n2++)
            ldsm4(b[n2][0], b[n2][1], b[n2][2], b[n2][3],
                  bAddr + (uint32_t)((n2 * 16 * XST + ks * 16) * 2));
#pragma unroll
        for (int mt = 0; mt < 2; mt++)
#pragma unroll
            for (int nt = 0; nt < 4; nt++)
                mma16816(acc[mt][nt], a[mt],
                         b[nt >> 1][(nt & 1) * 2], b[nt >> 1][(nt & 1) * 2 + 1]);
    }
    __syncthreads();

    {
        int rB = lane >> 2, cB = (lane & 3) * 2;
#pragma unroll
        for (int mt = 0; mt < 2; mt++) {
            int r = wm * 32 + mt * 16 + rB;
#pragma unroll
            for (int nt = 0; nt < 4; nt++) {
                int c = wn * 32 + nt * 8 + cB;
                Osm[c * 132 + r]            = acc[mt][nt][0];
                Osm[(c + 1) * 132 + r]      = acc[mt][nt][1];
                Osm[c * 132 + r + 8]        = acc[mt][nt][2];
                Osm[(c + 1) * 132 + r + 8]  = acc[mt][nt][3];
            }
        }
    }
    __syncthreads();

    {
        int n = tid >> 2, s0 = (tid & 3) * 32;
        bool isL = n < 32;
        int hh = isL ? n : n - 32;
        float bias = isL ? bleft[hh] : bright[hh];
        float scale = isL ? 1.f : (1.f / 128.f);
        __half* dst = (isL ? g_A : g_B) + (size_t)(l * 32 + hh) * 128 + s0;
#pragma unroll
        for (int q = 0; q < 4; q++) {
            float4 v0 = *(float4*)&Osm[n * 132 + s0 + q * 8];
            float4 v1 = *(float4*)&Osm[n * 132 + s0 + q * 8 + 4];
            uint4 pk;
            pk.x = pack2h((v0.x + bias) * scale, (v0.y + bias) * scale);
            pk.y = pack2h((v0.z + bias) * scale, (v0.w + bias) * scale);
            pk.z = pack2h((v1.x + bias) * scale, (v1.y + bias) * scale);
            pk.w = pack2h((v1.z + bias) * scale, (v1.w + bias) * scale);
            *(uint4*)(dst + q * 8) = pk;
        }
    }

#pragma unroll
    for (int it = 0; it < 2; it++) {
        int idx = blockIdx.x * 512 + it * 256 + tid;
        int k = idx >> 7, n = idx & 127;
        g_Wt[(size_t)n * 1024 + k] = __float2half_rn(wo[idx]);
    }
}

// ---------------------------------------------------------------------------
// Fused GEMM: same tile (16l x 8m), same SMEM, now 512 threads (16 warps,
// 4 warps/SMSP) to cover ldsm->mma latency. Phase A grid 2x8, phase B 4x4.
// ---------------------------------------------------------------------------
constexpr int STH   = 136;                      // halves
constexpr int B_OFF = 0;                        // [256][136]
constexpr int A_OFF = 256 * STH;                // 3 x [64][136]
constexpr int ABUF  = 64 * STH;
constexpr int G_OFF = A_OFF + 3 * ABUF;         // [128][136]
constexpr int W_OFF = G_OFF + 128 * STH;        // 2 x [128][136]
constexpr int WBUF  = 128 * STH;
constexpr int SMEM_FUSED = (W_OFF + 2 * WBUF) * 2;   // 226304 bytes

__global__ void __launch_bounds__(512, 1) fused_gemm_kernel(
    const float* __restrict__ pairin,
    const float* __restrict__ bo,
    float* __restrict__ outp)
{
    extern __shared__ __half smh[];
    float* smf = (float*)smh;
    uint32_t sb = smem_u32(smh);
    int tid = threadIdx.x, lane = tid & 31, w = tid >> 5;   // w: 0..15
    int bl = blockIdx.x, bm = blockIdx.y;

    const __half* gA = g_A + (size_t)(bl * 512) * 128;
    const __half* gB = g_B + (size_t)(bm * 256) * 128;

    auto prefetchW = [&](int c) {       // 2048 cpa16 over 512 threads
        uint32_t base = sb + (uint32_t)((W_OFF + (c & 1) * WBUF) * 2);
        int row = tid >> 2, sg0 = (tid & 3) * 4;
        const __half* src = g_Wt + (size_t)row * 1024 + c * 128 + sg0 * 8;
        uint32_t dst = base + (uint32_t)((row * STH + sg0 * 8) * 2);
#pragma unroll
        for (int sg = 0; sg < 4; sg++) cpa16(dst + sg * 16, src + sg * 8);
    };
    auto prefetchA = [&](int c) {       // 1024 cpa16 over 512 threads
        uint32_t base = sb + (uint32_t)((A_OFF + (c % 3) * ABUF) * 2);
#pragma unroll
        for (int it = 0; it < 2; it++) {
            int f = it * 512 + tid;
            int r = f >> 4, c8 = (f & 15) * 8;
            int grow = (r >> 2) * 32 + c * 4 + (r & 3);
            cpa16(base + (uint32_t)((r * STH + c8) * 2),
                  gA + (size_t)grow * 128 + c8);
        }
    };

    // prologue group: B + A0 + A1 + W0
#pragma unroll
    for (int it = 0; it < 8; it++) {
        int f = it * 512 + tid;
        int r = f >> 4, c8 = (f & 15) * 8;
        cpa16(sb + (uint32_t)((B_OFF + r * STH + c8) * 2),
              gB + (size_t)r * 128 + c8);
    }
    prefetchA(0);
    prefetchA(1);
    prefetchW(0);
    cpa_commit();

    float outAcc[2][4][4];
#pragma unroll
    for (int mt = 0; mt < 2; mt++)
#pragma unroll
        for (int nt = 0; nt < 4; nt++)
#pragma unroll
            for (int q = 0; q < 4; q++) outAcc[mt][nt][q] = 0.f;

    // ---- warp grids ----
    int wmA = w >> 3, wnA = w & 7;     // phase A: 2 (A-row groups) x 8 (m groups)
    int wmB = w >> 2, wnB = w & 3;     // phase B: 4 (pair groups) x 4 (n groups)

    uint32_t aAddrA0 = sb + (uint32_t)((A_OFF + (wmA * 32 + (lane & 15)) * STH
                                        + (lane >> 4) * 8) * 2);
    uint32_t bAddrA  = sb + (uint32_t)((B_OFF + (wnA * 32 + ((lane >> 4) & 1) * 8 + (lane & 7)) * STH
                                        + ((lane >> 3) & 1) * 8) * 2);
    uint32_t aAddrB  = sb + (uint32_t)((G_OFF + (wmB * 32 + (lane & 15)) * STH
                                        + (lane >> 4) * 8) * 2);
    uint32_t bAddrW0 = (uint32_t)((W_OFF + (wnB * 32 + ((lane >> 4) & 1) * 8 + (lane & 7)) * STH
                                   + ((lane >> 3) & 1) * 8) * 2);

    cpa_wait<0>();
    __syncthreads();

#pragma unroll 1
    for (int ic = 0; ic < 8; ic++) {
        if (ic > 0) __syncthreads();
        if (ic < 6) prefetchA(ic + 2);
        if (ic < 7) { prefetchW(ic + 1); cpa_commit(); }

        // ---- phase A: D[64 A-rows x 256 m-rows], K=128 s, f16 accum ----
        uint32_t aA = aAddrA0 + (uint32_t)((ic % 3) * ABUF * 2);
        uint32_t accA[2][4][2];
#pragma unroll
        for (int mt = 0; mt < 2; mt++)
#pragma unroll
            for (int nt = 0; nt < 4; nt++) {
                accA[mt][nt][0] = 0u; accA[mt][nt][1] = 0u;
            }

#pragma unroll
        for (int ks = 0; ks < 8; ks++) {
            uint32_t a[2][4], b[2][4];
#pragma unroll
            for (int mt = 0; mt < 2; mt++)
                ldsm4(a[mt][0], a[mt][1], a[mt][2], a[mt][3],
                      aA + (uint32_t)((mt * 16 * STH + ks * 16) * 2));
#pragma unroll
            for (int pr = 0; pr < 2; pr++)
                ldsm4(b[pr][0], b[pr][1], b[pr][2], b[pr][3],
                      bAddrA + (uint32_t)((pr * 16 * STH + ks * 16) * 2));
#pragma unroll
            for (int mt = 0; mt < 2; mt++)
#pragma unroll
                for (int nt = 0; nt < 4; nt++)
                    mma16816h(accA[mt][nt], a[mt],
                              b[nt >> 1][(nt & 1) * 2], b[nt >> 1][(nt & 1) * 2 + 1]);
        }

        // ---- scatter accA -> Gs[pair][ij_local] (half2 reg stores) ----
        {
            int rq = lane >> 2, cq = (lane & 3) * 2;
#pragma unroll
            for (int mt = 0; mt < 2; mt++) {
#pragma unroll
                for (int nt = 0; nt < 4; nt++) {
                    int cc = wnA * 32 + nt * 8 + cq;      // m-row: mloc*32+j
                    int mloc = cc >> 5, jj = cc & 31;
#pragma unroll
                    for (int rh = 0; rh < 2; rh++) {
                        int r = wmA * 32 + mt * 16 + rh * 8 + rq;   // lloc*4+di
                        int p = (r >> 2) * 8 + mloc;
                        int col = (r & 3) * 32 + jj;
                        *(uint32_t*)(smh + G_OFF + p * STH + col) = accA[mt][nt][rh];
                    }
                }
            }
        }
        if (ic < 7) { cpa_wait<1>(); } else { cpa_wait<0>(); }
        __syncthreads();

        // ---- phase B: D[128 pairs x 128 n] += Gs @ W[ic]^T (f32 accum) ----
        uint32_t sW = sb + bAddrW0 + (uint32_t)((ic & 1) * WBUF * 2);
#pragma unroll
        for (int ks = 0; ks < 8; ks++) {
            uint32_t a[2][4], b[2][4];
#pragma unroll
            for (int mt = 0; mt < 2; mt++)
                ldsm4(a[mt][0], a[mt][1], a[mt][2], a[mt][3],
                      aAddrB + (uint32_t)((mt * 16 * STH + ks * 16) * 2));
#pragma unroll
            for (int pr = 0; pr < 2; pr++)
                ldsm4(b[pr][0], b[pr][1], b[pr][2], b[pr][3],
                      sW + (uint32_t)((pr * 16 * STH + ks * 16) * 2));
#pragma unroll
            for (int mt = 0; mt < 2; mt++)
#pragma unroll
                for (int nt = 0; nt < 4; nt++)
                    mma16816(outAcc[mt][nt], a[mt],
                             b[nt >> 1][(nt & 1) * 2], b[nt >> 1][(nt & 1) * 2 + 1]);
        }
    }
    __syncthreads();

    // ---- epilogue: stage f32 (stride 132) in B region, coalesced writes ----
    {
        int rB = lane >> 2, nB = (lane & 3) * 2;
#pragma unroll
        for (int mt = 0; mt < 2; mt++) {
            int p = wmB * 32 + mt * 16 + rB;
#pragma unroll
            for (int nt = 0; nt < 4; nt++) {
                int nc = wnB * 32 + nt * 8 + nB;
                *(float2*)&smf[p * 132 + nc] =
                    make_float2(outAcc[mt][nt][0], outAcc[mt][nt][1]);
                *(float2*)&smf[(p + 8) * 132 + nc] =
                    make_float2(outAcc[mt][nt][2], outAcc[mt][nt][3]);
            }
        }
    }
    __syncthreads();

#pragma unroll
    for (int it = 0; it < 8; it++) {
        int f = it * 512 + tid;          // 4096 float4
        int p = f >> 5;                  // pair 0..127
        int c4 = (f & 31) * 4;
        int l = bl * 16 + (p >> 3);
        int m = bm * 8 + (p & 7);
        size_t o = ((size_t)(l * L_ + m)) * DP + c4;
        float4 v = *(float4*)&smf[p * 132 + c4];
        float4 pv = *(const float4*)&pairin[o];
        float4 bv = *(const float4*)&bo[c4];
        v.x += pv.x + bv.x; v.y += pv.y + bv.y;
        v.z += pv.z + bv.z; v.w += pv.w + bv.w;
        *(float4*)&outp[o] = v;
    }
}

// ---------------------------------------------------------------------------
// Launch
// ---------------------------------------------------------------------------
extern "C" void kernel_launch(void* const* d_in, const int* in_sizes, int n_in,
                              void* d_out, int out_size)
{
    const float* msa    = (const float*)d_in[0];
    const float* pairin = (const float*)d_in[1];
    const float* gamma  = (const float*)d_in[4];
    const float* beta   = (const float*)d_in[5];
    const float* wl     = (const float*)d_in[6];
    const float* bleft  = (const float*)d_in[7];
    const float* wr     = (const float*)d_in[8];
    const float* bright = (const float*)d_in[9];
    const float* wo     = (const float*)d_in[10];
    const float* bo     = (const float*)d_in[11];
    float* outp = (float*)d_out;

    int smemLn = 192 * XST * 2;   // 101376 bytes
    cudaFuncSetAttribute(ln_proj_kernel,
                         cudaFuncAttributeMaxDynamicSharedMemorySize, smemLn);
    cudaFuncSetAttribute(fused_gemm_kernel,
                         cudaFuncAttributeMaxDynamicSharedMemorySize, SMEM_FUSED);

    ln_proj_kernel<<<256, 256, smemLn>>>(msa, gamma, beta, wl, bleft, wr, bright, wo);
    fused_gemm_kernel<<<dim3(16, 32), 512, SMEM_FUSED>>>(pairin, bo, outp);
}